// round 15
// baseline (speedup 1.0000x reference)
#include <cuda_runtime.h>

#define TPB    128
#define ROWS   64
#define ST     68          // buffer row stride in floats (68 % 32 == 4 -> conflict-free)
#define NSTEPS 16

// ---- fragment-packed weight blocks (float2 = (b0,b1) per lane) ----
// blocks: Wq, Wk, Wv, z_out, zf1a, zf1b, zf2(K=128), Wca, yf1a, yf1b, yf2(K=128)
#define B_WQ    0
#define B_WK    2048
#define B_WV    4096
#define B_ZOUT  6144
#define B_ZF1A  8192
#define B_ZF1B  10240
#define B_ZF2   12288
#define B_WCA   16384
#define B_YF1A  18432
#define B_YF1B  20480
#define B_YF2   22528
#define B_TOT   26624

__device__ float2 g_Bhi[B_TOT];
__device__ float2 g_Blo[B_TOT];
__device__ float  g_Wca[64 * 64];
__device__ float  g_bca[64];

__device__ __forceinline__ float gelu_exact(float v) {
    return 0.5f * v * (1.0f + erff(v * 0.70710678118654752f));
}

// fp32 -> tf32 (rna) returning canonical fp32 bit pattern
__device__ __forceinline__ float tfr(float x) {
    unsigned u; asm("cvt.rna.tf32.f32 %0, %1;" : "=r"(u) : "f"(x));
    return __uint_as_float(u);
}
__device__ __forceinline__ void tsplit(float x, unsigned& hi, unsigned& lo) {
    asm("cvt.rna.tf32.f32 %0, %1;" : "=r"(hi) : "f"(x));
    float h = __uint_as_float(hi);
    asm("cvt.rna.tf32.f32 %0, %1;" : "=r"(lo) : "f"(x - h));
}

// m16n8k8 tf32 mma, D accumulate in place
__device__ __forceinline__ void mma8(float* d, const unsigned* a, unsigned b0, unsigned b1) {
    asm volatile("mma.sync.aligned.m16n8k8.row.col.f32.tf32.tf32.f32 "
                 "{%0,%1,%2,%3}, {%4,%5,%6,%7}, {%8,%9}, {%0,%1,%2,%3};"
                 : "+f"(d[0]), "+f"(d[1]), "+f"(d[2]), "+f"(d[3])
                 : "r"(a[0]), "r"(a[1]), "r"(a[2]), "r"(a[3]), "r"(b0), "r"(b1));
}

// FFMA2 helpers (scalar prologue only)
__device__ __forceinline__ void ffma2(unsigned long long& acc,
                                      unsigned long long a, unsigned long long b) {
    asm("fma.rn.f32x2 %0, %1, %2, %0;" : "+l"(acc) : "l"(a), "l"(b));
}
__device__ __forceinline__ float pairsum(unsigned long long v) {
    float lo, hi;
    asm("mov.b64 {%0, %1}, %2;" : "=f"(lo), "=f"(hi) : "l"(v));
    return lo + hi;
}

// ---------------------------------------------------------------------------
// gmma: split-tf32 GEMM unit. Warp covers all 4 M-tiles x NT N-tiles starting
// at tile jb. KT=8: K=64 from inA. KT=16: K=128 from inA(k<64)/inB(k>=64).
// mode: 0=store, 1=gelu+store, 2=add-dest.
// ---------------------------------------------------------------------------
template<int NT, int KT>
__device__ __forceinline__ void gmma(const float* inA, const float* inB,
                                     int boff,
                                     const float* __restrict__ bias,
                                     float* sOut, int mode, int jb, int lane)
{
    const int g = lane >> 2, t = lane & 3;
    float c[4][NT][4];
#pragma unroll
    for (int mt = 0; mt < 4; mt++)
#pragma unroll
        for (int jj = 0; jj < NT; jj++)
#pragma unroll
            for (int q = 0; q < 4; q++) c[mt][jj][q] = 0.f;

#pragma unroll 1
    for (int k0 = 0; k0 < KT; k0++) {
        const float* in = (KT == 16 && k0 >= 8) ? inB : inA;
        const float* rp = in + g * ST + ((k0 & 7) * 8 + t);
        unsigned ah[4][4], al[4][4];
#pragma unroll
        for (int mt = 0; mt < 4; mt++) {
            const float* q = rp + mt * 16 * ST;
            float a0 = q[0], a1 = q[8 * ST], a2 = q[4], a3 = q[8 * ST + 4];
            tsplit(a0, ah[mt][0], al[mt][0]);
            tsplit(a1, ah[mt][1], al[mt][1]);
            tsplit(a2, ah[mt][2], al[mt][2]);
            tsplit(a3, ah[mt][3], al[mt][3]);
        }
#pragma unroll
        for (int jj = 0; jj < NT; jj++) {
            int bi = boff + (k0 * 8 + jb + jj) * 32 + lane;
            float2 bh = __ldg(g_Bhi + bi);
            float2 bl = __ldg(g_Blo + bi);
            unsigned bh0 = __float_as_uint(bh.x), bh1 = __float_as_uint(bh.y);
            unsigned bl0 = __float_as_uint(bl.x), bl1 = __float_as_uint(bl.y);
#pragma unroll
            for (int mt = 0; mt < 4; mt++) {
                mma8(c[mt][jj], ah[mt], bh0, bh1);
                mma8(c[mt][jj], al[mt], bh0, bh1);
                mma8(c[mt][jj], ah[mt], bl0, bl1);
            }
        }
    }

#pragma unroll
    for (int mt = 0; mt < 4; mt++)
#pragma unroll
        for (int jj = 0; jj < NT; jj++) {
            int col = (jb + jj) * 8 + 2 * t;
            float bx = __ldg(bias + col), by = __ldg(bias + col + 1);
            int r0 = 16 * mt + g;
            float v0 = c[mt][jj][0] + bx, v1 = c[mt][jj][1] + by;
            float v2 = c[mt][jj][2] + bx, v3 = c[mt][jj][3] + by;
            if (mode == 1) {
                v0 = gelu_exact(v0); v1 = gelu_exact(v1);
                v2 = gelu_exact(v2); v3 = gelu_exact(v3);
            }
            float* p0 = sOut + r0 * ST + col;
            float* p1 = sOut + (r0 + 8) * ST + col;
            if (mode == 2) {
                float2 d0 = *(const float2*)p0, d1 = *(const float2*)p1;
                v0 += d0.x; v1 += d0.y; v2 += d1.x; v3 += d1.y;
            }
            *(float2*)p0 = make_float2(v0, v1);
            *(float2*)p1 = make_float2(v2, v3);
        }
}

// Prologue: 4-warp, K=200, input rows from GLOBAL x (row stride 200). Scalar.
__device__ __forceinline__ void gemm200(const float* __restrict__ gIn,
                                        const float* __restrict__ W,
                                        const float* __restrict__ bias, float* sOut,
                                        int w, int lane)
{
    const int ly = lane & 7, lx = (lane >> 3) & 3;
    const int c0 = 16 * w + 4 * lx;
    unsigned long long acc[8][4];
#pragma unroll
    for (int i = 0; i < 8; i++)
#pragma unroll
        for (int j = 0; j < 4; j++) acc[i][j] = 0ull;

    const float* ip = gIn + (size_t)ly * 200;
    const float* wp = W + c0 * 200;

#pragma unroll 1
    for (int k = 0; k < 200; k += 4) {
        ulonglong2 w4[4];
#pragma unroll
        for (int j = 0; j < 4; j++) w4[j] = __ldg((const ulonglong2*)(wp + j * 200 + k));
#pragma unroll
        for (int i = 0; i < 8; i++) {
            ulonglong2 b = __ldg((const ulonglong2*)(ip + (size_t)i * 8 * 200 + k));
#pragma unroll
            for (int j = 0; j < 4; j++) {
                ffma2(acc[i][j], w4[j].x, b.x);
                ffma2(acc[i][j], w4[j].y, b.y);
            }
        }
    }
    float4 bb = __ldg((const float4*)(bias + c0));
#pragma unroll
    for (int i = 0; i < 8; i++) {
        float* op = sOut + (ly + 8 * i) * ST + c0;
        float4 v;
        v.x = pairsum(acc[i][0]) + bb.x; v.y = pairsum(acc[i][1]) + bb.y;
        v.z = pairsum(acc[i][2]) + bb.z; v.w = pairsum(acc[i][3]) + bb.w;
        *(float4*)op = v;
    }
}

// LayerNorm, 2 threads per row (as in R13)
__device__ __forceinline__ void ln2(float* p, const float* __restrict__ g,
                                    const float* __restrict__ b, bool dogelu, int h)
{
    float4 v[8];
#pragma unroll
    for (int i = 0; i < 8; i++) v[i] = *(const float4*)(p + 4 * i);
    float s = 0.f;
#pragma unroll
    for (int i = 0; i < 8; i++) s += (v[i].x + v[i].y) + (v[i].z + v[i].w);
    s += __shfl_xor_sync(0xFFFFFFFFu, s, 1);
    float m = s * (1.0f / 64.0f);
    float qv = 0.f;
#pragma unroll
    for (int i = 0; i < 8; i++) {
        float dx = v[i].x - m, dy = v[i].y - m, dz = v[i].z - m, dw = v[i].w - m;
        qv = fmaf(dx, dx, qv); qv = fmaf(dy, dy, qv);
        qv = fmaf(dz, dz, qv); qv = fmaf(dw, dw, qv);
    }
    qv += __shfl_xor_sync(0xFFFFFFFFu, qv, 1);
    float inv = rsqrtf(qv * (1.0f / 64.0f) + 1e-5f);
#pragma unroll
    for (int i = 0; i < 8; i++) {
        float4 gg = __ldg((const float4*)(g + 32 * h + 4 * i));
        float4 bb = __ldg((const float4*)(b + 32 * h + 4 * i));
        float4 r;
        r.x = fmaf((v[i].x - m) * inv, gg.x, bb.x);
        r.y = fmaf((v[i].y - m) * inv, gg.y, bb.y);
        r.z = fmaf((v[i].z - m) * inv, gg.z, bb.z);
        r.w = fmaf((v[i].w - m) * inv, gg.w, bb.w);
        if (dogelu) {
            r.x = gelu_exact(r.x); r.y = gelu_exact(r.y);
            r.z = gelu_exact(r.z); r.w = gelu_exact(r.w);
        }
        *(float4*)(p + 4 * i) = r;
    }
}

// prep1: W_ca = y_out_w @ Wvy ; b_ca = y_out_w @ bvy + y_out_b
__global__ void prep_kernel(const float* __restrict__ y_out_w,
                            const float* __restrict__ y_in_w,
                            const float* __restrict__ y_in_b,
                            const float* __restrict__ y_out_b)
{
    int i = blockIdx.x;
    int k = threadIdx.x;
    const float* Wvy = y_in_w + 128 * 64;
    float a = 0.f;
    for (int j = 0; j < 64; j++)
        a = fmaf(y_out_w[i * 64 + j], Wvy[j * 64 + k], a);
    g_Wca[i * 64 + k] = a;
    if (k == 0) {
        float b = y_out_b[i];
        for (int j = 0; j < 64; j++) b = fmaf(y_out_w[i * 64 + j], y_in_b[128 + j], b);
        g_bca[i] = b;
    }
}

// prep2: pack all weight blocks into mma B-fragment order, split hi/lo
__global__ void prep2_kernel(const float* __restrict__ z_in_w,
                             const float* __restrict__ z_out_w,
                             const float* __restrict__ z_ffn_w1,
                             const float* __restrict__ z_ffn_w2,
                             const float* __restrict__ y_ffn_w1,
                             const float* __restrict__ y_ffn_w2)
{
    int idx = blockIdx.x * 256 + threadIdx.x;
    if (idx >= B_TOT) return;
    const float* W; int wrs, off;
    if      (idx < B_WK)   { W = z_in_w;          wrs = 64;  off = B_WQ; }
    else if (idx < B_WV)   { W = z_in_w + 4096;   wrs = 64;  off = B_WK; }
    else if (idx < B_ZOUT) { W = z_in_w + 8192;   wrs = 64;  off = B_WV; }
    else if (idx < B_ZF1A) { W = z_out_w;         wrs = 64;  off = B_ZOUT; }
    else if (idx < B_ZF1B) { W = z_ffn_w1;        wrs = 64;  off = B_ZF1A; }
    else if (idx < B_ZF2)  { W = z_ffn_w1 + 4096; wrs = 64;  off = B_ZF1B; }
    else if (idx < B_WCA)  { W = z_ffn_w2;        wrs = 128; off = B_ZF2; }
    else if (idx < B_YF1A) { W = g_Wca;           wrs = 64;  off = B_WCA; }
    else if (idx < B_YF1B) { W = y_ffn_w1;        wrs = 64;  off = B_YF1A; }
    else if (idx < B_YF2)  { W = y_ffn_w1 + 4096; wrs = 64;  off = B_YF1B; }
    else                   { W = y_ffn_w2;        wrs = 128; off = B_YF2; }
    int local = idx - off;
    int k0 = local >> 8;
    int rem = local & 255;
    int j = rem >> 5, lane = rem & 31;
    int g = lane >> 2, t = lane & 3;
    int n = j * 8 + g;
    float w0 = W[n * wrs + k0 * 8 + t];
    float w1 = W[n * wrs + k0 * 8 + t + 4];
    float h0 = tfr(w0), h1 = tfr(w1);
    g_Bhi[idx] = make_float2(h0, h1);
    g_Blo[idx] = make_float2(tfr(w0 - h0), tfr(w1 - h1));
}

// PAIR: warps 0,1 -> unit A; warps 2,3 -> unit B. NT=4 each warp.
#define PAIRM(inA, BA, bA, oA, mA, inB, BB, bB, oB, mB) do {                     \
    if (wid < 2) gmma<4, 8>((inA), (const float*)0, (BA), (bA), (oA), (mA), 4 * wid, lane);        \
    else         gmma<4, 8>((inB), (const float*)0, (BB), (bB), (oB), (mB), 4 * (wid - 2), lane);  \
    __syncthreads(); } while (0)

#define SINGM(in, BO, b, o, m) do {                                              \
    gmma<2, 8>((in), (const float*)0, (BO), (b), (o), (m), 2 * wid, lane);       \
    __syncthreads(); } while (0)

#define SINGM128(iA, iB, BO, b, o, m) do {                                       \
    gmma<2, 16>((iA), (iB), (BO), (b), (o), (m), 2 * wid, lane);                 \
    __syncthreads(); } while (0)

__global__ void __launch_bounds__(TPB, 2)
trm_kernel(const float* __restrict__ x,
           const float* __restrict__ W_in,     const float* __restrict__ b_in,
           const float* __restrict__ g_in,     const float* __restrict__ be_in,
           const float* __restrict__ z_in_b,
           const float* __restrict__ z_out_b,
           const float* __restrict__ z_ffn_b1, const float* __restrict__ z_ffn_b2,
           const float* __restrict__ zn1_g,    const float* __restrict__ zn1_b,
           const float* __restrict__ zn2_g,    const float* __restrict__ zn2_b,
           const float* __restrict__ y_ffn_b1, const float* __restrict__ y_ffn_b2,
           const float* __restrict__ yn1_g,    const float* __restrict__ yn1_b,
           const float* __restrict__ yn2_g,    const float* __restrict__ yn2_b,
           const float* __restrict__ W_out,    const float* __restrict__ b_out,
           float* __restrict__ out, int Btotal)
{
    extern __shared__ float sm[];
    float* sKX = sm + 0 * ROWS * ST;
    float* sVX = sm + 1 * ROWS * ST;
    float* sY  = sm + 2 * ROWS * ST;
    float* sZ  = sm + 3 * ROWS * ST;
    float* sSA = sm + 4 * ROWS * ST;
    float* sSB = sm + 5 * ROWS * ST;

    const int tid  = threadIdx.x;
    const int wid  = tid >> 5;
    const int lane = tid & 31;
    const int row0 = blockIdx.x * ROWS;
    const int erow = tid >> 1, eh = tid & 1;   // elementwise: 2 threads/row
    const int eoff = erow * ST + 32 * eh;

    const float* bq = z_in_b;
    const float* bk = z_in_b + 64;
    const float* bv = z_in_b + 128;

    // ---- prologue: x_proj = gelu(LN(x @ W_in^T + b_in)) -> SA ----
    gemm200(x + (size_t)row0 * 200, W_in, b_in, sSA, wid, lane);
    __syncthreads();
    ln2(sSA + eoff, g_in, be_in, true, eh);
    __syncthreads();
    // kx || vx
    PAIRM(sSA, B_WK, bk, sKX, 0,  sSA, B_WV, bv, sVX, 0);
    // zero y, z
    {
        float* yp = sY + eoff;
        float* zp = sZ + eoff;
        const float4 zz = make_float4(0.f, 0.f, 0.f, 0.f);
#pragma unroll
        for (int i = 0; i < 8; i++) { *(float4*)(yp + 4*i) = zz; *(float4*)(zp + 4*i) = zz; }
    }
    __syncthreads();

    // ---- 16 recursion steps ----
#pragma unroll 1
    for (int s = 0; s < NSTEPS; s++) {
        float qv[32];
        float s0[2], s2[2], wa0[2], wa1[2], wa2[2];

        // P1: q(z) -> SA || k(z) -> SB
        PAIRM(sZ, B_WQ, bq, sSA, 0,  sZ, B_WK, bk, sSB, 0);
        // E1: q -> regs; s0 = q.kx, s2 = q.kz
        {
            const float4* qp  = (const float4*)(sSA + eoff);
            const float4* kxp = (const float4*)(sKX + eoff);
            const float4* kzp = (const float4*)(sSB + eoff);
            s0[0] = s0[1] = s2[0] = s2[1] = 0.f;
#pragma unroll
            for (int i = 0; i < 8; i++) {
                float4 t = qp[i];
                qv[4*i] = t.x; qv[4*i+1] = t.y; qv[4*i+2] = t.z; qv[4*i+3] = t.w;
                int hh = i >> 2;
                float4 a = kxp[i];
                float4 c = kzp[i];
                s0[hh] = fmaf(t.x, a.x, fmaf(t.y, a.y, fmaf(t.z, a.z, fmaf(t.w, a.w, s0[hh]))));
                s2[hh] = fmaf(t.x, c.x, fmaf(t.y, c.y, fmaf(t.z, c.z, fmaf(t.w, c.w, s2[hh]))));
            }
        }
        __syncthreads();
        // P2: k(y) -> SB (q stays in registers)
        SINGM(sY, B_WK, bk, sSB, 0);
        // E2: s1 = q.ky ; softmax
        {
            const float4* kyp = (const float4*)(sSB + eoff);
            float s1[2] = {0.f, 0.f};
#pragma unroll
            for (int i = 0; i < 8; i++) {
                int hh = i >> 2;
                float4 a = kyp[i];
                s1[hh] = fmaf(qv[4*i], a.x, fmaf(qv[4*i+1], a.y,
                         fmaf(qv[4*i+2], a.z, fmaf(qv[4*i+3], a.w, s1[hh]))));
            }
#pragma unroll
            for (int hh = 0; hh < 2; hh++) {
                float a0 = s0[hh] * 0.25f, a1 = s1[hh] * 0.25f, a2 = s2[hh] * 0.25f;
                float mx = fmaxf(a0, fmaxf(a1, a2));
                float e0 = __expf(a0 - mx), e1 = __expf(a1 - mx), e2 = __expf(a2 - mx);
                float rs = 1.0f / (e0 + e1 + e2);
                wa0[hh] = e0 * rs; wa1[hh] = e1 * rs; wa2[hh] = e2 * rs;
            }
        }
        __syncthreads();
        // P3: v(y) -> SA || v(z) -> SB
        PAIRM(sY, B_WV, bv, sSA, 0,  sZ, B_WV, bv, sSB, 0);
        // E3: SA := wa0*vx + wa1*vy + wa2*vz
        {
            float* sap = sSA + eoff;
            const float4* sbp = (const float4*)(sSB + eoff);
            const float4* vxp = (const float4*)(sVX + eoff);
#pragma unroll
            for (int i = 0; i < 8; i++) {
                int hh = i >> 2;
                float4 a = vxp[i];
                float4 b2 = *(const float4*)(sap + 4*i);
                float4 c = sbp[i];
                float4 o;
                o.x = wa0[hh]*a.x + wa1[hh]*b2.x + wa2[hh]*c.x;
                o.y = wa0[hh]*a.y + wa1[hh]*b2.y + wa2[hh]*c.y;
                o.z = wa0[hh]*a.z + wa1[hh]*b2.z + wa2[hh]*c.z;
                o.w = wa0[hh]*a.w + wa1[hh]*b2.w + wa2[hh]*c.w;
                *(float4*)(sap + 4*i) = o;
            }
        }
        __syncthreads();
        // P4: z += SA @ z_out^T + b ; LN zn1
        SINGM(sSA, B_ZOUT, z_out_b, sZ, 2);
        ln2(sZ + eoff, zn1_g, zn1_b, false, eh);
        __syncthreads();
        // P5: FFN z hidden: gelu -> SA (dims 0-63) || SB (dims 64-127)
        PAIRM(sZ, B_ZF1A, z_ffn_b1, sSA, 1,  sZ, B_ZF1B, z_ffn_b1 + 64, sSB, 1);
        // P6: z += [SA|SB] @ w2^T + b2 ; LN zn2   (fused K=128)
        SINGM128(sSA, sSB, B_ZF2, z_ffn_b2, sZ, 2);
        ln2(sZ + eoff, zn2_g, zn2_b, false, eh);
        __syncthreads();
        // P7: y += z2 @ W_ca^T + b_ca ; LN yn1   [folded cross-attention]
        SINGM(sZ, B_WCA, g_bca, sY, 2);
        ln2(sY + eoff, yn1_g, yn1_b, false, eh);
        __syncthreads();
        // P8: FFN y hidden
        PAIRM(sY, B_YF1A, y_ffn_b1, sSA, 1,  sY, B_YF1B, y_ffn_b1 + 64, sSB, 1);
        // P9: y += [SA|SB] @ w2^T + b2 ; LN yn2   (fused K=128)
        SINGM128(sSA, sSB, B_YF2, y_ffn_b2, sY, 2);
        ln2(sY + eoff, yn2_g, yn2_b, false, eh);
        __syncthreads();
    }

    // ---- output: (y @ W_out^T + b_out)[:, 0] ----
    {
        const float4* yp = (const float4*)(sY + eoff);
        float acc = 0.f;
#pragma unroll
        for (int i = 0; i < 8; i++) {
            float4 v = yp[i];
            float4 w = __ldg((const float4*)(W_out + 32 * eh + 4 * i));
            acc = fmaf(v.x, w.x, fmaf(v.y, w.y, fmaf(v.z, w.z, fmaf(v.w, w.w, acc))));
        }
        acc += __shfl_xor_sync(0xFFFFFFFFu, acc, 1);
        int r = row0 + erow;
        if (eh == 0 && r < Btotal) out[r] = acc + __ldg(b_out);
    }
}

extern "C" void kernel_launch(void* const* d_in, const int* in_sizes, int n_in,
                              void* d_out, int out_size)
{
    const float* x        = (const float*)d_in[0];
    const float* W_in     = (const float*)d_in[1];
    const float* b_in     = (const float*)d_in[2];
    const float* g_in     = (const float*)d_in[3];
    const float* be_in    = (const float*)d_in[4];
    const float* z_in_w   = (const float*)d_in[5];
    const float* z_in_b   = (const float*)d_in[6];
    const float* z_out_w  = (const float*)d_in[7];
    const float* z_out_b  = (const float*)d_in[8];
    const float* z_ffn_w1 = (const float*)d_in[9];
    const float* z_ffn_b1 = (const float*)d_in[10];
    const float* z_ffn_w2 = (const float*)d_in[11];
    const float* z_ffn_b2 = (const float*)d_in[12];
    const float* zn1_g    = (const float*)d_in[13];
    const float* zn1_b    = (const float*)d_in[14];
    const float* zn2_g    = (const float*)d_in[15];
    const float* zn2_b    = (const float*)d_in[16];
    const float* y_in_w   = (const float*)d_in[17];
    const float* y_in_b   = (const float*)d_in[18];
    const float* y_out_w  = (const float*)d_in[19];
    const float* y_out_b  = (const float*)d_in[20];
    const float* y_ffn_w1 = (const float*)d_in[21];
    const float* y_ffn_b1 = (const float*)d_in[22];
    const float* y_ffn_w2 = (const float*)d_in[23];
    const float* y_ffn_b2 = (const float*)d_in[24];
    const float* yn1_g    = (const float*)d_in[25];
    const float* yn1_b    = (const float*)d_in[26];
    const float* yn2_g    = (const float*)d_in[27];
    const float* yn2_b    = (const float*)d_in[28];
    const float* W_out    = (const float*)d_in[29];
    const float* b_out    = (const float*)d_in[30];
    float* out = (float*)d_out;

    int B = in_sizes[0] / 200;

    prep_kernel<<<64, 64>>>(y_out_w, y_in_w, y_in_b, y_out_b);
    prep2_kernel<<<(B_TOT + 255) / 256, 256>>>(z_in_w, z_out_w, z_ffn_w1, z_ffn_w2,
                                               y_ffn_w1, y_ffn_w2);

    size_t smem = (size_t)6 * ROWS * ST * sizeof(float);   // 104448 B -> 2 CTAs/SM
    cudaFuncSetAttribute(trm_kernel, cudaFuncAttributeMaxDynamicSharedMemorySize, (int)smem);

    dim3 grid((B + ROWS - 1) / ROWS);
    trm_kernel<<<grid, TPB, smem>>>(x, W_in, b_in, g_in, be_in,
                                    z_in_b, z_out_b,
                                    z_ffn_b1, z_ffn_b2,
                                    zn1_g, zn1_b, zn2_g, zn2_b,
                                    y_ffn_b1, y_ffn_b2,
                                    yn1_g, yn1_b, yn2_g, yn2_b,
                                    W_out, b_out, out, B);
}

// round 16
// speedup vs baseline: 1.0530x; 1.0530x over previous
#include <cuda_runtime.h>

#define TPB    256
#define ROWS   64
#define ST     68          // buffer row stride in floats (68 % 32 == 4 -> conflict-free)
#define NSTEPS 16

__device__ float g_Wca[64 * 64];
__device__ float g_bca[64];

__device__ __forceinline__ float gelu_exact(float v) {
    return 0.5f * v * (1.0f + erff(v * 0.70710678118654752f));
}
__device__ __forceinline__ void ffma2(unsigned long long& acc,
                                      unsigned long long a, unsigned long long b) {
    asm("fma.rn.f32x2 %0, %1, %2, %0;" : "+l"(acc) : "l"(a), "l"(b));
}
__device__ __forceinline__ float pairsum(unsigned long long v) {
    float lo, hi;
    asm("mov.b64 {%0, %1}, %2;" : "=f"(lo), "=f"(hi) : "l"(v));
    return lo + hi;
}

// ---------------------------------------------------------------------------
// gemm16: warp computes cols [16w, 16w+16) x rows 0..63, K=64 (or wrs/kof for
// FFN-w2 K=128 halves). 8x4 per-lane tile, k-packed FFMA2.
// mode: 0=store, 1=gelu+store, 2=add-dest.
// ---------------------------------------------------------------------------
__device__ __forceinline__ void gemm16(const float* sIn, const float* __restrict__ W,
                                       int wrs, int kof,
                                       const float* __restrict__ bias, float* sOut,
                                       int mode, int w, int lane)
{
    const int ly = lane & 7, lx = (lane >> 3) & 3;
    const int c0 = 16 * w + 4 * lx;
    unsigned long long acc[8][4];
#pragma unroll
    for (int i = 0; i < 8; i++)
#pragma unroll
        for (int j = 0; j < 4; j++) acc[i][j] = 0ull;

    const float* ip = sIn + ly * ST;
    const float* wp = W + c0 * wrs + kof;

#pragma unroll 1
    for (int k = 0; k < 64; k += 4) {
        ulonglong2 w4[4];
#pragma unroll
        for (int j = 0; j < 4; j++) w4[j] = __ldg((const ulonglong2*)(wp + j * wrs + k));
#pragma unroll
        for (int i = 0; i < 8; i++) {
            ulonglong2 b = *(const ulonglong2*)(ip + i * (8 * ST) + k);
#pragma unroll
            for (int j = 0; j < 4; j++) {
                ffma2(acc[i][j], w4[j].x, b.x);
                ffma2(acc[i][j], w4[j].y, b.y);
            }
        }
    }

    float4 bb;
    if (bias) bb = __ldg((const float4*)(bias + c0));
    else      bb = make_float4(0.f, 0.f, 0.f, 0.f);
#pragma unroll
    for (int i = 0; i < 8; i++) {
        float* op = sOut + (ly + 8 * i) * ST + c0;
        float4 v;
        v.x = pairsum(acc[i][0]) + bb.x; v.y = pairsum(acc[i][1]) + bb.y;
        v.z = pairsum(acc[i][2]) + bb.z; v.w = pairsum(acc[i][3]) + bb.w;
        if (mode == 1) {
            v.x = gelu_exact(v.x); v.y = gelu_exact(v.y);
            v.z = gelu_exact(v.z); v.w = gelu_exact(v.w);
        } else if (mode == 2) {
            float4 d = *(const float4*)op;
            v.x += d.x; v.y += d.y; v.z += d.z; v.w += d.w;
        }
        *(float4*)op = v;
    }
}

// ---------------------------------------------------------------------------
// gemm8: 8-WARP single unit; warp w computes cols [8w, 8w+8).
// lane: ly = lane&15 (rows ly+16i, i<4), lx = lane>>4 (cols 8w+4lx).
// ---------------------------------------------------------------------------
__device__ __forceinline__ void gemm8(const float* sIn, const float* __restrict__ W,
                                      int wrs, int kof,
                                      const float* __restrict__ bias, float* sOut,
                                      int mode, int w, int lane)
{
    const int ly = lane & 15, lx = lane >> 4;
    const int c0 = 8 * w + 4 * lx;
    unsigned long long acc[4][4];
#pragma unroll
    for (int i = 0; i < 4; i++)
#pragma unroll
        for (int j = 0; j < 4; j++) acc[i][j] = 0ull;

    const float* ip = sIn + ly * ST;
    const float* wp = W + c0 * wrs + kof;

#pragma unroll 1
    for (int k = 0; k < 64; k += 4) {
        ulonglong2 w4[4];
#pragma unroll
        for (int j = 0; j < 4; j++) w4[j] = __ldg((const ulonglong2*)(wp + j * wrs + k));
#pragma unroll
        for (int i = 0; i < 4; i++) {
            ulonglong2 b = *(const ulonglong2*)(ip + i * (16 * ST) + k);
#pragma unroll
            for (int j = 0; j < 4; j++) {
                ffma2(acc[i][j], w4[j].x, b.x);
                ffma2(acc[i][j], w4[j].y, b.y);
            }
        }
    }

    float4 bb;
    if (bias) bb = __ldg((const float4*)(bias + c0));
    else      bb = make_float4(0.f, 0.f, 0.f, 0.f);
#pragma unroll
    for (int i = 0; i < 4; i++) {
        float* op = sOut + (ly + 16 * i) * ST + c0;
        float4 v;
        v.x = pairsum(acc[i][0]) + bb.x; v.y = pairsum(acc[i][1]) + bb.y;
        v.z = pairsum(acc[i][2]) + bb.z; v.w = pairsum(acc[i][3]) + bb.w;
        if (mode == 1) {
            v.x = gelu_exact(v.x); v.y = gelu_exact(v.y);
            v.z = gelu_exact(v.z); v.w = gelu_exact(v.w);
        } else if (mode == 2) {
            float4 d = *(const float4*)op;
            v.x += d.x; v.y += d.y; v.z += d.z; v.w += d.w;
        }
        *(float4*)op = v;
    }
}

// Prologue: 8-warp, K=200, input rows from GLOBAL x (row stride 200).
__device__ __forceinline__ void gemm200(const float* __restrict__ gIn,
                                        const float* __restrict__ W,
                                        const float* __restrict__ bias, float* sOut,
                                        int w, int lane)
{
    const int ly = lane & 15, lx = lane >> 4;
    const int c0 = 8 * w + 4 * lx;
    unsigned long long acc[4][4];
#pragma unroll
    for (int i = 0; i < 4; i++)
#pragma unroll
        for (int j = 0; j < 4; j++) acc[i][j] = 0ull;

    const float* ip = gIn + (size_t)ly * 200;
    const float* wp = W + c0 * 200;

#pragma unroll 1
    for (int k = 0; k < 200; k += 4) {
        ulonglong2 w4[4];
#pragma unroll
        for (int j = 0; j < 4; j++) w4[j] = __ldg((const ulonglong2*)(wp + j * 200 + k));
#pragma unroll
        for (int i = 0; i < 4; i++) {
            ulonglong2 b = __ldg((const ulonglong2*)(ip + (size_t)i * 16 * 200 + k));
#pragma unroll
            for (int j = 0; j < 4; j++) {
                ffma2(acc[i][j], w4[j].x, b.x);
                ffma2(acc[i][j], w4[j].y, b.y);
            }
        }
    }
    float4 bb = __ldg((const float4*)(bias + c0));
#pragma unroll
    for (int i = 0; i < 4; i++) {
        float* op = sOut + (ly + 16 * i) * ST + c0;
        float4 v;
        v.x = pairsum(acc[i][0]) + bb.x; v.y = pairsum(acc[i][1]) + bb.y;
        v.z = pairsum(acc[i][2]) + bb.z; v.w = pairsum(acc[i][3]) + bb.w;
        *(float4*)op = v;
    }
}

// LayerNorm, 4 threads per row: p = row base + 16*eq; reduce via shfl 1,2.
__device__ __forceinline__ void ln4(float* p, const float* __restrict__ g,
                                    const float* __restrict__ b, bool dogelu, int eq)
{
    float4 v[4];
#pragma unroll
    for (int i = 0; i < 4; i++) v[i] = *(const float4*)(p + 4 * i);
    float s = 0.f;
#pragma unroll
    for (int i = 0; i < 4; i++) s += (v[i].x + v[i].y) + (v[i].z + v[i].w);
    s += __shfl_xor_sync(0xFFFFFFFFu, s, 1);
    s += __shfl_xor_sync(0xFFFFFFFFu, s, 2);
    float m = s * (1.0f / 64.0f);
    float qv = 0.f;
#pragma unroll
    for (int i = 0; i < 4; i++) {
        float dx = v[i].x - m, dy = v[i].y - m, dz = v[i].z - m, dw = v[i].w - m;
        qv = fmaf(dx, dx, qv); qv = fmaf(dy, dy, qv);
        qv = fmaf(dz, dz, qv); qv = fmaf(dw, dw, qv);
    }
    qv += __shfl_xor_sync(0xFFFFFFFFu, qv, 1);
    qv += __shfl_xor_sync(0xFFFFFFFFu, qv, 2);
    float inv = rsqrtf(qv * (1.0f / 64.0f) + 1e-5f);
#pragma unroll
    for (int i = 0; i < 4; i++) {
        float4 gg = __ldg((const float4*)(g + 16 * eq + 4 * i));
        float4 bb = __ldg((const float4*)(b + 16 * eq + 4 * i));
        float4 r;
        r.x = fmaf((v[i].x - m) * inv, gg.x, bb.x);
        r.y = fmaf((v[i].y - m) * inv, gg.y, bb.y);
        r.z = fmaf((v[i].z - m) * inv, gg.z, bb.z);
        r.w = fmaf((v[i].w - m) * inv, gg.w, bb.w);
        if (dogelu) {
            r.x = gelu_exact(r.x); r.y = gelu_exact(r.y);
            r.z = gelu_exact(r.z); r.w = gelu_exact(r.w);
        }
        *(float4*)(p + 4 * i) = r;
    }
}

// prep: W_ca = y_out_w @ Wvy ; b_ca = y_out_w @ bvy + y_out_b
__global__ void prep_kernel(const float* __restrict__ y_out_w,
                            const float* __restrict__ y_in_w,
                            const float* __restrict__ y_in_b,
                            const float* __restrict__ y_out_b)
{
    int i = blockIdx.x;
    int k = threadIdx.x;
    const float* Wvy = y_in_w + 128 * 64;
    float a = 0.f;
    for (int j = 0; j < 64; j++)
        a = fmaf(y_out_w[i * 64 + j], Wvy[j * 64 + k], a);
    g_Wca[i * 64 + k] = a;
    if (k == 0) {
        float b = y_out_b[i];
        for (int j = 0; j < 64; j++) b = fmaf(y_out_w[i * 64 + j], y_in_b[128 + j], b);
        g_bca[i] = b;
    }
}

// PAIR: warps 0-3 -> unit A; warps 4-7 -> unit B (each warp 16 cols).
#define PAIR(inA, WA, bA, oA, mA, inB, WB, bB, oB, mB) do {                     \
    if (wid < 4) gemm16((inA), (WA), 64, 0, (bA), (oA), (mA), wid, lane);       \
    else         gemm16((inB), (WB), 64, 0, (bB), (oB), (mB), wid - 4, lane);   \
    __syncthreads(); } while (0)

#define SINGLE(in, W, wrs, kof, b, o, m) do {                                   \
    gemm8((in), (W), (wrs), (kof), (b), (o), (m), wid, lane);                   \
    __syncthreads(); } while (0)

__global__ void __launch_bounds__(TPB, 2)
trm_kernel(const float* __restrict__ x,
           const float* __restrict__ W_in,     const float* __restrict__ b_in,
           const float* __restrict__ g_in,     const float* __restrict__ be_in,
           const float* __restrict__ z_in_w,   const float* __restrict__ z_in_b,
           const float* __restrict__ z_out_w,  const float* __restrict__ z_out_b,
           const float* __restrict__ z_ffn_w1, const float* __restrict__ z_ffn_b1,
           const float* __restrict__ z_ffn_w2, const float* __restrict__ z_ffn_b2,
           const float* __restrict__ zn1_g,    const float* __restrict__ zn1_b,
           const float* __restrict__ zn2_g,    const float* __restrict__ zn2_b,
           const float* __restrict__ y_ffn_w1, const float* __restrict__ y_ffn_b1,
           const float* __restrict__ y_ffn_w2, const float* __restrict__ y_ffn_b2,
           const float* __restrict__ yn1_g,    const float* __restrict__ yn1_b,
           const float* __restrict__ yn2_g,    const float* __restrict__ yn2_b,
           const float* __restrict__ W_out,    const float* __restrict__ b_out,
           float* __restrict__ out, int Btotal)
{
    extern __shared__ float sm[];
    float* sKX = sm + 0 * ROWS * ST;
    float* sVX = sm + 1 * ROWS * ST;
    float* sY  = sm + 2 * ROWS * ST;
    float* sZ  = sm + 3 * ROWS * ST;
    float* sSA = sm + 4 * ROWS * ST;
    float* sSB = sm + 5 * ROWS * ST;

    const int tid  = threadIdx.x;
    const int wid  = tid >> 5;
    const int lane = tid & 31;
    const int row0 = blockIdx.x * ROWS;
    const int erow = tid >> 2, eq = tid & 3;   // elementwise: 4 threads/row, head eq
    const int eoff = erow * ST + 16 * eq;

    const float* Wq = z_in_w;
    const float* Wk = z_in_w + 64 * 64;
    const float* Wv = z_in_w + 128 * 64;
    const float* bq = z_in_b;
    const float* bk = z_in_b + 64;
    const float* bv = z_in_b + 128;

    // ---- prologue: x_proj = gelu(LN(x @ W_in^T + b_in)) -> SA ----
    gemm200(x + (size_t)row0 * 200, W_in, b_in, sSA, wid, lane);
    __syncthreads();
    ln4(sSA + eoff, g_in, be_in, true, eq);
    __syncthreads();
    // kx || vx
    PAIR(sSA, Wk, bk, sKX, 0,  sSA, Wv, bv, sVX, 0);
    // zero y, z
    {
        float* yp = sY + eoff;
        float* zp = sZ + eoff;
        const float4 zz = make_float4(0.f, 0.f, 0.f, 0.f);
#pragma unroll
        for (int i = 0; i < 4; i++) { *(float4*)(yp + 4*i) = zz; *(float4*)(zp + 4*i) = zz; }
    }
    __syncthreads();

    // ---- 16 recursion steps ----
#pragma unroll 1
    for (int s = 0; s < NSTEPS; s++) {
        float s0, s2, wa0, wa1, wa2;

        // P1: q(z) -> SA || k(z) -> SB
        PAIR(sZ, Wq, bq, sSA, 0,  sZ, Wk, bk, sSB, 0);
        // E1: s0 = q.kx, s2 = q.kz (head eq, fully local)
        {
            const float4* qp  = (const float4*)(sSA + eoff);
            const float4* kxp = (const float4*)(sKX + eoff);
            const float4* kzp = (const float4*)(sSB + eoff);
            s0 = 0.f; s2 = 0.f;
#pragma unroll
            for (int i = 0; i < 4; i++) {
                float4 t = qp[i];
                float4 a = kxp[i];
                float4 c = kzp[i];
                s0 = fmaf(t.x, a.x, fmaf(t.y, a.y, fmaf(t.z, a.z, fmaf(t.w, a.w, s0))));
                s2 = fmaf(t.x, c.x, fmaf(t.y, c.y, fmaf(t.z, c.z, fmaf(t.w, c.w, s2))));
            }
        }
        __syncthreads();
        // P2: k(y) -> SB (q preserved in SA)
        SINGLE(sY, Wk, 64, 0, bk, sSB, 0);
        // E2: s1 = q.ky (q re-read from SA) ; softmax
        {
            const float4* qp  = (const float4*)(sSA + eoff);
            const float4* kyp = (const float4*)(sSB + eoff);
            float s1 = 0.f;
#pragma unroll
            for (int i = 0; i < 4; i++) {
                float4 t = qp[i];
                float4 a = kyp[i];
                s1 = fmaf(t.x, a.x, fmaf(t.y, a.y, fmaf(t.z, a.z, fmaf(t.w, a.w, s1))));
            }
            float a0 = s0 * 0.25f, a1 = s1 * 0.25f, a2 = s2 * 0.25f;
            float mx = fmaxf(a0, fmaxf(a1, a2));
            float e0 = __expf(a0 - mx), e1 = __expf(a1 - mx), e2 = __expf(a2 - mx);
            float rs = 1.0f / (e0 + e1 + e2);
            wa0 = e0 * rs; wa1 = e1 * rs; wa2 = e2 * rs;
        }
        __syncthreads();
        // P3: v(y) -> SA || v(z) -> SB
        PAIR(sY, Wv, bv, sSA, 0,  sZ, Wv, bv, sSB, 0);
        // E3: SA := wa0*vx + wa1*vy(SA) + wa2*vz(SB)
        {
            float* sap = sSA + eoff;
            const float4* sbp = (const float4*)(sSB + eoff);
            const float4* vxp = (const float4*)(sVX + eoff);
#pragma unroll
            for (int i = 0; i < 4; i++) {
                float4 a = vxp[i];
                float4 b2 = *(const float4*)(sap + 4*i);
                float4 c = sbp[i];
                float4 o;
                o.x = wa0*a.x + wa1*b2.x + wa2*c.x;
                o.y = wa0*a.y + wa1*b2.y + wa2*c.y;
                o.z = wa0*a.z + wa1*b2.z + wa2*c.z;
                o.w = wa0*a.w + wa1*b2.w + wa2*c.w;
                *(float4*)(sap + 4*i) = o;
            }
        }
        __syncthreads();
        // P4: z += SA @ z_out_w^T + z_out_b ; LN zn1
        SINGLE(sSA, z_out_w, 64, 0, z_out_b, sZ, 2);
        ln4(sZ + eoff, zn1_g, zn1_b, false, eq);
        __syncthreads();
        // P5: FFN z hidden: gelu -> SA (dims 0-63) || SB (dims 64-127)
        PAIR(sZ, z_ffn_w1, z_ffn_b1, sSA, 1,  sZ, z_ffn_w1 + 64*64, z_ffn_b1 + 64, sSB, 1);
        // P6: z += [SA|SB] @ w2^T + b2 ; LN zn2
        gemm8(sSA, z_ffn_w2, 128, 0,  z_ffn_b2, sZ, 2, wid, lane);
        gemm8(sSB, z_ffn_w2, 128, 64, (const float*)0, sZ, 2, wid, lane);
        __syncthreads();
        ln4(sZ + eoff, zn2_g, zn2_b, false, eq);
        __syncthreads();
        // P7: y += z2 @ W_ca^T + b_ca ; LN yn1   [folded cross-attention]
        SINGLE(sZ, g_Wca, 64, 0, g_bca, sY, 2);
        ln4(sY + eoff, yn1_g, yn1_b, false, eq);
        __syncthreads();
        // P8: FFN y hidden
        PAIR(sY, y_ffn_w1, y_ffn_b1, sSA, 1,  sY, y_ffn_w1 + 64*64, y_ffn_b1 + 64, sSB, 1);
        // P9: y += [SA|SB] @ w2^T + b2 ; LN yn2
        gemm8(sSA, y_ffn_w2, 128, 0,  y_ffn_b2, sY, 2, wid, lane);
        gemm8(sSB, y_ffn_w2, 128, 64, (const float*)0, sY, 2, wid, lane);
        __syncthreads();
        ln4(sY + eoff, yn2_g, yn2_b, false, eq);
        __syncthreads();
    }

    // ---- output: (y @ W_out^T + b_out)[:, 0] ----
    {
        const float4* yp = (const float4*)(sY + eoff);
        float acc = 0.f;
#pragma unroll
        for (int i = 0; i < 4; i++) {
            float4 v = yp[i];
            float4 w = __ldg((const float4*)(W_out + 16 * eq + 4 * i));
            acc = fmaf(v.x, w.x, fmaf(v.y, w.y, fmaf(v.z, w.z, fmaf(v.w, w.w, acc))));
        }
        acc += __shfl_xor_sync(0xFFFFFFFFu, acc, 1);
        acc += __shfl_xor_sync(0xFFFFFFFFu, acc, 2);
        int r = row0 + erow;
        if (eq == 0 && r < Btotal) out[r] = acc + __ldg(b_out);
    }
}

extern "C" void kernel_launch(void* const* d_in, const int* in_sizes, int n_in,
                              void* d_out, int out_size)
{
    const float* x        = (const float*)d_in[0];
    const float* W_in     = (const float*)d_in[1];
    const float* b_in     = (const float*)d_in[2];
    const float* g_in     = (const float*)d_in[3];
    const float* be_in    = (const float*)d_in[4];
    const float* z_in_w   = (const float*)d_in[5];
    const float* z_in_b   = (const float*)d_in[6];
    const float* z_out_w  = (const float*)d_in[7];
    const float* z_out_b  = (const float*)d_in[8];
    const float* z_ffn_w1 = (const float*)d_in[9];
    const float* z_ffn_b1 = (const float*)d_in[10];
    const float* z_ffn_w2 = (const float*)d_in[11];
    const float* z_ffn_b2 = (const float*)d_in[12];
    const float* zn1_g    = (const float*)d_in[13];
    const float* zn1_b    = (const float*)d_in[14];
    const float* zn2_g    = (const float*)d_in[15];
    const float* zn2_b    = (const float*)d_in[16];
    const float* y_in_w   = (const float*)d_in[17];
    const float* y_in_b   = (const float*)d_in[18];
    const float* y_out_w  = (const float*)d_in[19];
    const float* y_out_b  = (const float*)d_in[20];
    const float* y_ffn_w1 = (const float*)d_in[21];
    const float* y_ffn_b1 = (const float*)d_in[22];
    const float* y_ffn_w2 = (const float*)d_in[23];
    const float* y_ffn_b2 = (const float*)d_in[24];
    const float* yn1_g    = (const float*)d_in[25];
    const float* yn1_b    = (const float*)d_in[26];
    const float* yn2_g    = (const float*)d_in[27];
    const float* yn2_b    = (const float*)d_in[28];
    const float* W_out    = (const float*)d_in[29];
    const float* b_out    = (const float*)d_in[30];
    float* out = (float*)d_out;

    int B = in_sizes[0] / 200;

    prep_kernel<<<64, 64>>>(y_out_w, y_in_w, y_in_b, y_out_b);

    size_t smem = (size_t)6 * ROWS * ST * sizeof(float);   // 104448 B -> 2 CTAs/SM
    cudaFuncSetAttribute(trm_kernel, cudaFuncAttributeMaxDynamicSharedMemorySize, (int)smem);

    dim3 grid((B + ROWS - 1) / ROWS);
    trm_kernel<<<grid, TPB, smem>>>(x, W_in, b_in, g_in, be_in,
                                    z_in_w, z_in_b, z_out_w, z_out_b,
                                    z_ffn_w1, z_ffn_b1, z_ffn_w2, z_ffn_b2,
                                    zn1_g, zn1_b, zn2_g, zn2_b,
                                    y_ffn_w1, y_ffn_b1, y_ffn_w2, y_ffn_b2,
                                    yn1_g, yn1_b, yn2_g, yn2_b,
                                    W_out, b_out, out, B);
}

// round 17
// speedup vs baseline: 1.2327x; 1.1707x over previous
#include <cuda_runtime.h>

#define TPB    128
#define ROWS   64
#define ST     68          // buffer row stride in floats (68 % 32 == 4 -> conflict-free)
#define NSTEPS 16

__device__ float g_Wca[64 * 64];
__device__ float g_bca[64];

__device__ __forceinline__ float gelu_exact(float v) {
    return 0.5f * v * (1.0f + erff(v * 0.70710678118654752f));
}
__device__ __forceinline__ void ffma2(unsigned long long& acc,
                                      unsigned long long a, unsigned long long b) {
    asm("fma.rn.f32x2 %0, %1, %2, %0;" : "+l"(acc) : "l"(a), "l"(b));
}
__device__ __forceinline__ float pairsum(unsigned long long v) {
    float lo, hi;
    asm("mov.b64 {%0, %1}, %2;" : "=f"(lo), "=f"(hi) : "l"(v));
    return lo + hi;
}
__device__ __forceinline__ void pf_l1(const void* p) {
    asm volatile("prefetch.global.L1 [%0];" :: "l"(p));
}

// ---------------------------------------------------------------------------
// gemm32: ONE WARP computes rows 0..63 x cols [32ch, 32ch+32); 8x8 per-lane
// tile, k-packed FFMA2 accumulators. mode: 0=store, 1=gelu+store, 2=add-dest.
// Warp weight slice = 8KB contiguous -> 2 L1 prefetches/lane warm it.
// ---------------------------------------------------------------------------
__device__ __forceinline__ void gemm32(const float* sIn, const float* __restrict__ W,
                                       const float* __restrict__ bias, float* sOut,
                                       int mode, int ch, int lane)
{
    const int ly = lane & 7, lx = lane >> 3;
    const int c0 = 32 * ch + 8 * lx;

    // prefetch this warp's whole weight slice (64 lines of 128B)
    {
        const float* pb = W + (32 * ch) * 64;
        pf_l1(pb + lane * 32);
        pf_l1(pb + (32 + lane) * 32);
    }

    unsigned long long acc[8][8];
#pragma unroll
    for (int i = 0; i < 8; i++)
#pragma unroll
        for (int j = 0; j < 8; j++) acc[i][j] = 0ull;

    const float* ip = sIn + ly * ST;
    const float* wp = W + c0 * 64;

#pragma unroll 1
    for (int k = 0; k < 64; k += 4) {
        ulonglong2 w[8];
#pragma unroll
        for (int j = 0; j < 8; j++) w[j] = __ldg((const ulonglong2*)(wp + j * 64 + k));
#pragma unroll
        for (int i = 0; i < 8; i++) {
            ulonglong2 b = *(const ulonglong2*)(ip + i * (8 * ST) + k);
#pragma unroll
            for (int j = 0; j < 8; j++) {
                ffma2(acc[i][j], w[j].x, b.x);
                ffma2(acc[i][j], w[j].y, b.y);
            }
        }
    }

    float bb[8];
#pragma unroll
    for (int j = 0; j < 8; j++) bb[j] = __ldg(bias + c0 + j);
#pragma unroll
    for (int i = 0; i < 8; i++) {
        float* op = sOut + (ly + 8 * i) * ST + c0;
#pragma unroll
        for (int q = 0; q < 2; q++) {
            float4 v;
            v.x = pairsum(acc[i][4*q+0]) + bb[4*q+0];
            v.y = pairsum(acc[i][4*q+1]) + bb[4*q+1];
            v.z = pairsum(acc[i][4*q+2]) + bb[4*q+2];
            v.w = pairsum(acc[i][4*q+3]) + bb[4*q+3];
            if (mode == 1) {
                v.x = gelu_exact(v.x); v.y = gelu_exact(v.y);
                v.z = gelu_exact(v.z); v.w = gelu_exact(v.w);
            } else if (mode == 2) {
                float4 d = *(const float4*)(op + 4*q);
                v.x += d.x; v.y += d.y; v.z += d.z; v.w += d.w;
            }
            *(float4*)(op + 4*q) = v;
        }
    }
}

// ---------------------------------------------------------------------------
// gemm16: 4-WARP single unit; warp w computes cols [16w, 16w+16).
// Warp weight slice = 16 rows x 64 used floats -> 32 lines; 1 prefetch/lane.
// ---------------------------------------------------------------------------
__device__ __forceinline__ void gemm16(const float* sIn, const float* __restrict__ W,
                                       int wrs, int kof,
                                       const float* __restrict__ bias, float* sOut,
                                       int mode, int w, int lane)
{
    const int ly = lane & 7, lx = (lane >> 3) & 3;
    const int c0 = 16 * w + 4 * lx;

    {
        const float* pb = W + (16 * w) * wrs + kof;
        pf_l1(pb + (lane >> 1) * wrs + (lane & 1) * 32);
    }

    unsigned long long acc[8][4];
#pragma unroll
    for (int i = 0; i < 8; i++)
#pragma unroll
        for (int j = 0; j < 4; j++) acc[i][j] = 0ull;

    const float* ip = sIn + ly * ST;
    const float* wp = W + c0 * wrs + kof;

#pragma unroll 1
    for (int k = 0; k < 64; k += 4) {
        ulonglong2 w4[4];
#pragma unroll
        for (int j = 0; j < 4; j++) w4[j] = __ldg((const ulonglong2*)(wp + j * wrs + k));
#pragma unroll
        for (int i = 0; i < 8; i++) {
            ulonglong2 b = *(const ulonglong2*)(ip + i * (8 * ST) + k);
#pragma unroll
            for (int j = 0; j < 4; j++) {
                ffma2(acc[i][j], w4[j].x, b.x);
                ffma2(acc[i][j], w4[j].y, b.y);
            }
        }
    }

    float4 bb;
    if (bias) bb = __ldg((const float4*)(bias + c0));
    else      bb = make_float4(0.f, 0.f, 0.f, 0.f);
#pragma unroll
    for (int i = 0; i < 8; i++) {
        float* op = sOut + (ly + 8 * i) * ST + c0;
        float4 v;
        v.x = pairsum(acc[i][0]) + bb.x; v.y = pairsum(acc[i][1]) + bb.y;
        v.z = pairsum(acc[i][2]) + bb.z; v.w = pairsum(acc[i][3]) + bb.w;
        if (mode == 1) {
            v.x = gelu_exact(v.x); v.y = gelu_exact(v.y);
            v.z = gelu_exact(v.z); v.w = gelu_exact(v.w);
        } else if (mode == 2) {
            float4 d = *(const float4*)op;
            v.x += d.x; v.y += d.y; v.z += d.z; v.w += d.w;
        }
        *(float4*)op = v;
    }
}

// Prologue: 4-warp, K=200, input rows from GLOBAL x (row stride 200).
__device__ __forceinline__ void gemm200(const float* __restrict__ gIn,
                                        const float* __restrict__ W,
                                        const float* __restrict__ bias, float* sOut,
                                        int w, int lane)
{
    const int ly = lane & 7, lx = (lane >> 3) & 3;
    const int c0 = 16 * w + 4 * lx;
    unsigned long long acc[8][4];
#pragma unroll
    for (int i = 0; i < 8; i++)
#pragma unroll
        for (int j = 0; j < 4; j++) acc[i][j] = 0ull;

    const float* ip = gIn + (size_t)ly * 200;
    const float* wp = W + c0 * 200;

#pragma unroll 1
    for (int k = 0; k < 200; k += 4) {
        ulonglong2 w4[4];
#pragma unroll
        for (int j = 0; j < 4; j++) w4[j] = __ldg((const ulonglong2*)(wp + j * 200 + k));
#pragma unroll
        for (int i = 0; i < 8; i++) {
            ulonglong2 b = __ldg((const ulonglong2*)(ip + (size_t)i * 8 * 200 + k));
#pragma unroll
            for (int j = 0; j < 4; j++) {
                ffma2(acc[i][j], w4[j].x, b.x);
                ffma2(acc[i][j], w4[j].y, b.y);
            }
        }
    }
    float4 bb = __ldg((const float4*)(bias + c0));
#pragma unroll
    for (int i = 0; i < 8; i++) {
        float* op = sOut + (ly + 8 * i) * ST + c0;
        float4 v;
        v.x = pairsum(acc[i][0]) + bb.x; v.y = pairsum(acc[i][1]) + bb.y;
        v.z = pairsum(acc[i][2]) + bb.z; v.w = pairsum(acc[i][3]) + bb.w;
        *(float4*)op = v;
    }
}

// LayerNorm, 2 threads per row: p = row base + 32*h; pair-reduce via shfl.bfly(1).
__device__ __forceinline__ void ln2(float* p, const float* __restrict__ g,
                                    const float* __restrict__ b, bool dogelu, int h)
{
    float4 v[8];
#pragma unroll
    for (int i = 0; i < 8; i++) v[i] = *(const float4*)(p + 4 * i);
    float s = 0.f;
#pragma unroll
    for (int i = 0; i < 8; i++) s += (v[i].x + v[i].y) + (v[i].z + v[i].w);
    s += __shfl_xor_sync(0xFFFFFFFFu, s, 1);
    float m = s * (1.0f / 64.0f);
    float qv = 0.f;
#pragma unroll
    for (int i = 0; i < 8; i++) {
        float dx = v[i].x - m, dy = v[i].y - m, dz = v[i].z - m, dw = v[i].w - m;
        qv = fmaf(dx, dx, qv); qv = fmaf(dy, dy, qv);
        qv = fmaf(dz, dz, qv); qv = fmaf(dw, dw, qv);
    }
    qv += __shfl_xor_sync(0xFFFFFFFFu, qv, 1);
    float inv = rsqrtf(qv * (1.0f / 64.0f) + 1e-5f);
#pragma unroll
    for (int i = 0; i < 8; i++) {
        float4 gg = __ldg((const float4*)(g + 32 * h + 4 * i));
        float4 bb = __ldg((const float4*)(b + 32 * h + 4 * i));
        float4 r;
        r.x = fmaf((v[i].x - m) * inv, gg.x, bb.x);
        r.y = fmaf((v[i].y - m) * inv, gg.y, bb.y);
        r.z = fmaf((v[i].z - m) * inv, gg.z, bb.z);
        r.w = fmaf((v[i].w - m) * inv, gg.w, bb.w);
        if (dogelu) {
            r.x = gelu_exact(r.x); r.y = gelu_exact(r.y);
            r.z = gelu_exact(r.z); r.w = gelu_exact(r.w);
        }
        *(float4*)(p + 4 * i) = r;
    }
}

// prep: W_ca = y_out_w @ Wvy ; b_ca = y_out_w @ bvy + y_out_b
__global__ void prep_kernel(const float* __restrict__ y_out_w,
                            const float* __restrict__ y_in_w,
                            const float* __restrict__ y_in_b,
                            const float* __restrict__ y_out_b)
{
    int i = blockIdx.x;
    int k = threadIdx.x;
    const float* Wvy = y_in_w + 128 * 64;
    float a = 0.f;
    for (int j = 0; j < 64; j++)
        a = fmaf(y_out_w[i * 64 + j], Wvy[j * 64 + k], a);
    g_Wca[i * 64 + k] = a;
    if (k == 0) {
        float b = y_out_b[i];
        for (int j = 0; j < 64; j++) b = fmaf(y_out_w[i * 64 + j], y_in_b[128 + j], b);
        g_bca[i] = b;
    }
}

// pair-phase macro: warps 0,1 -> unit A (col halves 0/1); warps 2,3 -> unit B.
#define PAIR(inA, WA, bA, oA, mA, inB, WB, bB, oB, mB) do {            \
    const float* gi; const float* gw; const float* gb; float* go; int gm; \
    if (wid < 2) { gi = (inA); gw = (WA); gb = (bA); go = (oA); gm = (mA); } \
    else         { gi = (inB); gw = (WB); gb = (bB); go = (oB); gm = (mB); } \
    gemm32(gi, gw, gb, go, gm, wid & 1, lane);                          \
    __syncthreads(); } while (0)

#define SINGLE(in, W, wrs, kof, b, o, m) do {                          \
    gemm16((in), (W), (wrs), (kof), (b), (o), (m), wid, lane);         \
    __syncthreads(); } while (0)

__global__ void __launch_bounds__(TPB, 2)
trm_kernel(const float* __restrict__ x,
           const float* __restrict__ W_in,     const float* __restrict__ b_in,
           const float* __restrict__ g_in,     const float* __restrict__ be_in,
           const float* __restrict__ z_in_w,   const float* __restrict__ z_in_b,
           const float* __restrict__ z_out_w,  const float* __restrict__ z_out_b,
           const float* __restrict__ z_ffn_w1, const float* __restrict__ z_ffn_b1,
           const float* __restrict__ z_ffn_w2, const float* __restrict__ z_ffn_b2,
           const float* __restrict__ zn1_g,    const float* __restrict__ zn1_b,
           const float* __restrict__ zn2_g,    const float* __restrict__ zn2_b,
           const float* __restrict__ y_ffn_w1, const float* __restrict__ y_ffn_b1,
           const float* __restrict__ y_ffn_w2, const float* __restrict__ y_ffn_b2,
           const float* __restrict__ yn1_g,    const float* __restrict__ yn1_b,
           const float* __restrict__ yn2_g,    const float* __restrict__ yn2_b,
           const float* __restrict__ W_out,    const float* __restrict__ b_out,
           float* __restrict__ out, int Btotal)
{
    extern __shared__ float sm[];
    float* sKX = sm + 0 * ROWS * ST;
    float* sVX = sm + 1 * ROWS * ST;
    float* sY  = sm + 2 * ROWS * ST;
    float* sZ  = sm + 3 * ROWS * ST;
    float* sSA = sm + 4 * ROWS * ST;
    float* sSB = sm + 5 * ROWS * ST;

    const int tid  = threadIdx.x;
    const int wid  = tid >> 5;
    const int lane = tid & 31;
    const int row0 = blockIdx.x * ROWS;
    const int erow = tid >> 1, eh = tid & 1;   // elementwise: 2 threads/row
    const int eoff = erow * ST + 32 * eh;

    const float* Wq = z_in_w;
    const float* Wk = z_in_w + 64 * 64;
    const float* Wv = z_in_w + 128 * 64;
    const float* bq = z_in_b;
    const float* bk = z_in_b + 64;
    const float* bv = z_in_b + 128;

    // ---- prologue: x_proj = gelu(LN(x @ W_in^T + b_in)) -> SA ----
    gemm200(x + (size_t)row0 * 200, W_in, b_in, sSA, wid, lane);
    __syncthreads();
    ln2(sSA + eoff, g_in, be_in, true, eh);
    __syncthreads();
    // kx = xp@Wk^T+bk  ||  vx = xp@Wv^T+bv
    PAIR(sSA, Wk, bk, sKX, 0,  sSA, Wv, bv, sVX, 0);
    // zero y, z (all 128 threads)
    {
        float* yp = sY + eoff;
        float* zp = sZ + eoff;
        const float4 zz = make_float4(0.f, 0.f, 0.f, 0.f);
#pragma unroll
        for (int i = 0; i < 8; i++) { *(float4*)(yp + 4*i) = zz; *(float4*)(zp + 4*i) = zz; }
    }
    __syncthreads();

    // ---- 16 recursion steps ----
#pragma unroll 1
    for (int s = 0; s < NSTEPS; s++) {
        float qv[32];
        float s0[2], s2[2], wa0[2], wa1[2], wa2[2];

        // P1: q(z) -> SA  ||  k(z) -> SB
        PAIR(sZ, Wq, bq, sSA, 0,  sZ, Wk, bk, sSB, 0);
        // E1: load q half to regs; s0 = q.kx, s2 = q.kz
        {
            const float4* qp  = (const float4*)(sSA + eoff);
            const float4* kxp = (const float4*)(sKX + eoff);
            const float4* kzp = (const float4*)(sSB + eoff);
            s0[0] = s0[1] = s2[0] = s2[1] = 0.f;
#pragma unroll
            for (int i = 0; i < 8; i++) {
                float4 t = qp[i];
                qv[4*i] = t.x; qv[4*i+1] = t.y; qv[4*i+2] = t.z; qv[4*i+3] = t.w;
                int hh = i >> 2;
                float4 a = kxp[i];
                float4 c = kzp[i];
                s0[hh] = fmaf(t.x, a.x, fmaf(t.y, a.y, fmaf(t.z, a.z, fmaf(t.w, a.w, s0[hh]))));
                s2[hh] = fmaf(t.x, c.x, fmaf(t.y, c.y, fmaf(t.z, c.z, fmaf(t.w, c.w, s2[hh]))));
            }
        }
        __syncthreads();
        // P2: k(y) -> SB (q stays in registers)
        SINGLE(sY, Wk, 64, 0, bk, sSB, 0);
        // E2: s1 = q.ky ; softmax
        {
            const float4* kyp = (const float4*)(sSB + eoff);
            float s1[2] = {0.f, 0.f};
#pragma unroll
            for (int i = 0; i < 8; i++) {
                int hh = i >> 2;
                float4 a = kyp[i];
                s1[hh] = fmaf(qv[4*i], a.x, fmaf(qv[4*i+1], a.y,
                         fmaf(qv[4*i+2], a.z, fmaf(qv[4*i+3], a.w, s1[hh]))));
            }
#pragma unroll
            for (int hh = 0; hh < 2; hh++) {
                float a0 = s0[hh] * 0.25f, a1 = s1[hh] * 0.25f, a2 = s2[hh] * 0.25f;
                float mx = fmaxf(a0, fmaxf(a1, a2));
                float e0 = __expf(a0 - mx), e1 = __expf(a1 - mx), e2 = __expf(a2 - mx);
                float rs = 1.0f / (e0 + e1 + e2);
                wa0[hh] = e0 * rs; wa1[hh] = e1 * rs; wa2[hh] = e2 * rs;
            }
        }
        __syncthreads();
        // P3: v(y) -> SA  ||  v(z) -> SB
        PAIR(sY, Wv, bv, sSA, 0,  sZ, Wv, bv, sSB, 0);
        // E3: SA := wa0*vx + wa1*vy + wa2*vz
        {
            float* sap = sSA + eoff;
            const float4* sbp = (const float4*)(sSB + eoff);
            const float4* vxp = (const float4*)(sVX + eoff);
#pragma unroll
            for (int i = 0; i < 8; i++) {
                int hh = i >> 2;
                float4 a = vxp[i];
                float4 b2 = *(const float4*)(sap + 4*i);
                float4 c = sbp[i];
                float4 o;
                o.x = wa0[hh]*a.x + wa1[hh]*b2.x + wa2[hh]*c.x;
                o.y = wa0[hh]*a.y + wa1[hh]*b2.y + wa2[hh]*c.y;
                o.z = wa0[hh]*a.z + wa1[hh]*b2.z + wa2[hh]*c.z;
                o.w = wa0[hh]*a.w + wa1[hh]*b2.w + wa2[hh]*c.w;
                *(float4*)(sap + 4*i) = o;
            }
        }
        __syncthreads();
        // P4: z += SA @ z_out_w^T + z_out_b ; LN zn1
        SINGLE(sSA, z_out_w, 64, 0, z_out_b, sZ, 2);
        ln2(sZ + eoff, zn1_g, zn1_b, false, eh);
        __syncthreads();
        // P5: FFN z hidden: gelu -> SA (dims 0-63) || SB (dims 64-127)
        PAIR(sZ, z_ffn_w1, z_ffn_b1, sSA, 1,  sZ, z_ffn_w1 + 64*64, z_ffn_b1 + 64, sSB, 1);
        // P6: z += [SA|SB] @ w2^T + b2 ; LN zn2
        gemm16(sSA, z_ffn_w2, 128, 0,  z_ffn_b2, sZ, 2, wid, lane);
        gemm16(sSB, z_ffn_w2, 128, 64, (const float*)0, sZ, 2, wid, lane);
        __syncthreads();
        ln2(sZ + eoff, zn2_g, zn2_b, false, eh);
        __syncthreads();
        // P7: y += z2 @ W_ca^T + b_ca ; LN yn1   [folded cross-attention]
        SINGLE(sZ, g_Wca, 64, 0, g_bca, sY, 2);
        ln2(sY + eoff, yn1_g, yn1_b, false, eh);
        __syncthreads();
        // P8: FFN y hidden
        PAIR(sY, y_ffn_w1, y_ffn_b1, sSA, 1,  sY, y_ffn_w1 + 64*64, y_ffn_b1 + 64, sSB, 1);
        // P9: y += [SA|SB] @ w2^T + b2 ; LN yn2
        gemm16(sSA, y_ffn_w2, 128, 0,  y_ffn_b2, sY, 2, wid, lane);
        gemm16(sSB, y_ffn_w2, 128, 64, (const float*)0, sY, 2, wid, lane);
        __syncthreads();
        ln2(sY + eoff, yn2_g, yn2_b, false, eh);
        __syncthreads();
    }

    // ---- output: (y @ W_out^T + b_out)[:, 0] ----
    {
        const float4* yp = (const float4*)(sY + eoff);
        float acc = 0.f;
#pragma unroll
        for (int i = 0; i < 8; i++) {
            float4 v = yp[i];
            float4 w = __ldg((const float4*)(W_out + 32 * eh + 4 * i));
            acc = fmaf(v.x, w.x, fmaf(v.y, w.y, fmaf(v.z, w.z, fmaf(v.w, w.w, acc))));
        }
        acc += __shfl_xor_sync(0xFFFFFFFFu, acc, 1);
        int r = row0 + erow;
        if (eh == 0 && r < Btotal) out[r] = acc + __ldg(b_out);
    }
}

extern "C" void kernel_launch(void* const* d_in, const int* in_sizes, int n_in,
                              void* d_out, int out_size)
{
    const float* x        = (const float*)d_in[0];
    const float* W_in     = (const float*)d_in[1];
    const float* b_in     = (const float*)d_in[2];
    const float* g_in     = (const float*)d_in[3];
    const float* be_in    = (const float*)d_in[4];
    const float* z_in_w   = (const float*)d_in[5];
    const float* z_in_b   = (const float*)d_in[6];
    const float* z_out_w  = (const float*)d_in[7];
    const float* z_out_b  = (const float*)d_in[8];
    const float* z_ffn_w1 = (const float*)d_in[9];
    const float* z_ffn_b1 = (const float*)d_in[10];
    const float* z_ffn_w2 = (const float*)d_in[11];
    const float* z_ffn_b2 = (const float*)d_in[12];
    const float* zn1_g    = (const float*)d_in[13];
    const float* zn1_b    = (const float*)d_in[14];
    const float* zn2_g    = (const float*)d_in[15];
    const float* zn2_b    = (const float*)d_in[16];
    const float* y_in_w   = (const float*)d_in[17];
    const float* y_in_b   = (const float*)d_in[18];
    const float* y_out_w  = (const float*)d_in[19];
    const float* y_out_b  = (const float*)d_in[20];
    const float* y_ffn_w1 = (const float*)d_in[21];
    const float* y_ffn_b1 = (const float*)d_in[22];
    const float* y_ffn_w2 = (const float*)d_in[23];
    const float* y_ffn_b2 = (const float*)d_in[24];
    const float* yn1_g    = (const float*)d_in[25];
    const float* yn1_b    = (const float*)d_in[26];
    const float* yn2_g    = (const float*)d_in[27];
    const float* yn2_b    = (const float*)d_in[28];
    const float* W_out    = (const float*)d_in[29];
    const float* b_out    = (const float*)d_in[30];
    float* out = (float*)d_out;

    int B = in_sizes[0] / 200;

    prep_kernel<<<64, 64>>>(y_out_w, y_in_w, y_in_b, y_out_b);

    size_t smem = (size_t)6 * ROWS * ST * sizeof(float);   // 104448 B -> 2 CTAs/SM
    cudaFuncSetAttribute(trm_kernel, cudaFuncAttributeMaxDynamicSharedMemorySize, (int)smem);

    dim3 grid((B + ROWS - 1) / ROWS);
    trm_kernel<<<grid, TPB, smem>>>(x, W_in, b_in, g_in, be_in,
                                    z_in_w, z_in_b, z_out_w, z_out_b,
                                    z_ffn_w1, z_ffn_b1, z_ffn_w2, z_ffn_b2,
                                    zn1_g, zn1_b, zn2_g, zn2_b,
                                    y_ffn_w1, y_ffn_b1, y_ffn_w2, y_ffn_b2,
                                    yn1_g, yn1_b, yn2_g, yn2_b,
                                    W_out, b_out, out, B);
}